// round 4
// baseline (speedup 1.0000x reference)
#include <cuda_runtime.h>
#include <cuda_bf16.h>
#include <math.h>

#define NU 100000
#define NI 50000
#define NE 200000
#define NR 64
#define DD 64
#define KK 16
#define NEDGE 2000000
#define NL 2
#define NB 4096
#define REG 1.0e-4f

// ---------------- scratch (static device globals; no allocation) ----------------
__device__ float g_aggu[2][NU * DD];   // agg_u per layer (becomes next u_cur; needed for u_sum)
__device__ float g_inext[2][NI * DD];  // i_cur after each layer (needed for i_sum)
__device__ float g_aggi[NI * DD];      // agg_i, reused per layer
__device__ float g_kg[NI * DD];        // kg_item, reused per layer
__device__ float g_rW[NR * DD];        // rel_emb @ W_eff (per layer, recomputed)
__device__ float g_rb[NR];             // rel_emb . Wk_b
__device__ double g_acc[2];            // [0]=sum log(sigmoid+eps), [1]=sum l2

// ---------------- vector red helper ----------------
__device__ __forceinline__ void red_add_v4(float* p, float a, float b, float c, float d) {
    asm volatile("red.global.add.v4.f32 [%0], {%1,%2,%3,%4};"
                 :: "l"(p), "f"(a), "f"(b), "f"(c), "f"(d) : "memory");
}

// ---------------- 1) per-layer relation projection: rW[n,d] = sum_o rel[n,o]*(Wk[o,d]+Wk[o,D+d]) ----
__global__ void rw_kernel(const float* __restrict__ rel, const float* __restrict__ Wk,
                          const float* __restrict__ Wkb) {
    int n = blockIdx.x;
    int d = threadIdx.x;
    float s = 0.f;
    #pragma unroll 8
    for (int o = 0; o < DD; o++) {
        float rv = __ldg(&rel[n * DD + o]);
        s += rv * (__ldg(&Wk[o * 2 * DD + d]) + __ldg(&Wk[o * 2 * DD + DD + d]));
    }
    g_rW[n * DD + d] = s;
    if (d == 0) {
        float t = 0.f;
        for (int o = 0; o < DD; o++) t += __ldg(&rel[n * DD + o]) * __ldg(&Wkb[o]);
        g_rb[n] = t;
    }
}

// ---------------- 2) KG attention: warp per item ----------------
__global__ void attn_kernel(const float* __restrict__ icur, const float* __restrict__ ent,
                            const int* __restrict__ kgr, const int* __restrict__ kge) {
    __shared__ float srW[NR * DD];
    __shared__ float srb[NR];
    for (int t = threadIdx.x; t < NR * DD; t += blockDim.x) srW[t] = g_rW[t];
    if (threadIdx.x < NR) srb[threadIdx.x] = g_rb[threadIdx.x];
    __syncthreads();

    int warp = threadIdx.x >> 5, lane = threadIdx.x & 31;
    int i = blockIdx.x * (blockDim.x >> 5) + warp;
    if (i >= NI) return;

    float2 ic = *(const float2*)&icur[i * DD + lane * 2];
    float sc[KK];
    float2 vv[KK];
    #pragma unroll
    for (int k = 0; k < KK; k++) {
        int e  = __ldg(&kge[i * KK + k]);
        int rn = __ldg(&kgr[i * KK + k]);
        float2 v = *(const float2*)&ent[(size_t)e * DD + lane * 2];
        vv[k] = v;
        float p = srW[rn * DD + lane * 2] * v.x * ic.x + srW[rn * DD + lane * 2 + 1] * v.y * ic.y;
        #pragma unroll
        for (int off = 16; off; off >>= 1) p += __shfl_xor_sync(0xffffffffu, p, off);
        p += srb[rn];
        sc[k] = (p > 0.f) ? p : 0.2f * p;  // leaky_relu(0.2)
    }
    // softmax over K (identical in all lanes)
    float m = sc[0];
    #pragma unroll
    for (int k = 1; k < KK; k++) m = fmaxf(m, sc[k]);
    float den = 0.f;
    #pragma unroll
    for (int k = 0; k < KK; k++) { sc[k] = __expf(sc[k] - m); den += sc[k]; }
    float inv = 1.f / den;
    float2 acc = make_float2(0.f, 0.f);
    #pragma unroll
    for (int k = 0; k < KK; k++) { acc.x += sc[k] * vv[k].x; acc.y += sc[k] * vv[k].y; }
    *(float2*)&g_kg[i * DD + lane * 2] = make_float2(acc.x * inv, acc.y * inv);
}

// ---------------- 3) edge aggregation: 2 edges/thread, 16 threads/edge-chunk, float4 + red.v4 ----
__global__ void edge_kernel(const float* __restrict__ ucur, const float* __restrict__ icur,
                            const int* __restrict__ eu, const int* __restrict__ ei,
                            const float* __restrict__ nw,
                            float* __restrict__ aggu, float* __restrict__ aggi) {
    const int HALF = NEDGE / 2;
    int gid = blockIdx.x * blockDim.x + threadIdx.x;
    int e0 = gid >> 4;
    int c = (gid & 15) * 4;
    if (e0 >= HALF) return;
    int e1 = e0 + HALF;

    // front-batch all index/weight/gather loads for both edges (MLP_eff ~ 2x)
    int u0  = __ldg(&eu[e0]);
    int i0  = __ldg(&ei[e0]);
    int u1  = __ldg(&eu[e1]);
    int i1  = __ldg(&ei[e1]);
    float n0 = __ldg(&nw[e0]);
    float n1 = __ldg(&nw[e1]);

    float4 uv0 = __ldg((const float4*)&ucur[u0 * DD + c]);
    float4 iv0 = __ldg((const float4*)&icur[i0 * DD + c]);
    float4 uv1 = __ldg((const float4*)&ucur[u1 * DD + c]);
    float4 iv1 = __ldg((const float4*)&icur[i1 * DD + c]);

    red_add_v4(&aggi[i0 * DD + c], n0 * uv0.x, n0 * uv0.y, n0 * uv0.z, n0 * uv0.w);
    red_add_v4(&aggu[u0 * DD + c], n0 * iv0.x, n0 * iv0.y, n0 * iv0.z, n0 * iv0.w);
    red_add_v4(&aggi[i1 * DD + c], n1 * uv1.x, n1 * uv1.y, n1 * uv1.z, n1 * uv1.w);
    red_add_v4(&aggu[u1 * DD + c], n1 * iv1.x, n1 * iv1.y, n1 * iv1.z, n1 * iv1.w);
}

// ---------------- 4) gate + combine: i_next = g*kg + (1-g)*agg_i ----------------
__global__ void combine_kernel(const float* __restrict__ Wa, const float* __restrict__ Wab,
                               const float* __restrict__ Wb, const float* __restrict__ Wbb,
                               float* __restrict__ out) {
    __shared__ float sWa[DD * 65];
    __shared__ float sWb[DD * 65];
    __shared__ float sab[DD], sbb[DD];
    __shared__ float sKg[4 * DD], sAg[4 * DD];
    for (int t = threadIdx.x; t < DD * DD; t += 256) {
        int o = t >> 6, d = t & 63;
        sWa[o * 65 + d] = Wa[t];
        sWb[o * 65 + d] = Wb[t];
    }
    if (threadIdx.x < DD) { sab[threadIdx.x] = Wab[threadIdx.x]; sbb[threadIdx.x] = Wbb[threadIdx.x]; }
    __syncthreads();

    int o = threadIdx.x & 63, j = threadIdx.x >> 6;
    int blockStart = blockIdx.x * 64;
    for (int base = 0; base < 64; base += 4) {
        int it0 = blockStart + base;
        int idx = it0 * DD + threadIdx.x;
        __syncthreads();
        if (idx < NI * DD) { sKg[threadIdx.x] = g_kg[idx]; sAg[threadIdx.x] = g_aggi[idx]; }
        __syncthreads();
        int item = it0 + j;
        if (item < NI) {
            float a = 0.f, b = 0.f;
            #pragma unroll
            for (int d = 0; d < DD; d++) {
                a += sWa[o * 65 + d] * sKg[j * DD + d];
                b += sWb[o * 65 + d] * sAg[j * DD + d];
            }
            float z = a + sab[o] + b + sbb[o];
            float gate = 1.f / (1.f + __expf(-z));
            float kv = sKg[j * DD + o], av = sAg[j * DD + o];
            out[item * DD + o] = gate * kv + (1.f - gate) * av;
        }
    }
}

// ---------------- 5) loss reduction ----------------
__global__ void zero_acc_kernel() { g_acc[0] = 0.0; g_acc[1] = 0.0; }

__global__ void loss_kernel(const float* __restrict__ uemb, const float* __restrict__ iemb,
                            const float* __restrict__ U0, const float* __restrict__ U1,
                            const float* __restrict__ I0, const float* __restrict__ I1,
                            const int* __restrict__ user, const int* __restrict__ pos,
                            const int* __restrict__ neg) {
    int warp = (blockIdx.x * blockDim.x + threadIdx.x) >> 5;
    int lane = threadIdx.x & 31;
    if (warp >= NB) return;
    int u = __ldg(&user[warp]), p = __ldg(&pos[warp]), n = __ldg(&neg[warp]);
    int du = u * DD + lane * 2, dp = p * DD + lane * 2, dn = n * DD + lane * 2;

    float2 a = *(const float2*)&uemb[du];
    float2 b = *(const float2*)&U0[du];
    float2 c = *(const float2*)&U1[du];
    float2 ue = make_float2(a.x + b.x + c.x, a.y + b.y + c.y);

    a = *(const float2*)&iemb[dp]; b = *(const float2*)&I0[dp]; c = *(const float2*)&I1[dp];
    float2 pe = make_float2(a.x + b.x + c.x, a.y + b.y + c.y);

    a = *(const float2*)&iemb[dn]; b = *(const float2*)&I0[dn]; c = *(const float2*)&I1[dn];
    float2 ne = make_float2(a.x + b.x + c.x, a.y + b.y + c.y);

    float ps = ue.x * pe.x + ue.y * pe.y;
    float ns = ue.x * ne.x + ue.y * ne.y;
    float l2 = ue.x * ue.x + ue.y * ue.y + pe.x * pe.x + pe.y * pe.y + ne.x * ne.x + ne.y * ne.y;
    #pragma unroll
    for (int off = 16; off; off >>= 1) {
        ps += __shfl_xor_sync(0xffffffffu, ps, off);
        ns += __shfl_xor_sync(0xffffffffu, ns, off);
        l2 += __shfl_xor_sync(0xffffffffu, l2, off);
    }
    if (lane == 0) {
        float diff = ps - ns;
        float sig = 1.f / (1.f + expf(-diff));
        atomicAdd(&g_acc[0], (double)logf(sig + 1e-10f));
        atomicAdd(&g_acc[1], (double)l2);
    }
}

__global__ void final_kernel(float* __restrict__ out) {
    double bpr = -g_acc[0] / (double)NB;
    double l2  = g_acc[1] / (double)NB;
    out[0] = (float)(bpr + (double)REG * l2);
}

// ---------------- host ----------------
extern "C" void kernel_launch(void* const* d_in, const int* in_sizes, int n_in,
                              void* d_out, int out_size) {
    const float* user_emb = (const float*)d_in[0];
    const float* item_emb = (const float*)d_in[1];
    const float* ent_emb  = (const float*)d_in[2];
    const float* rel_emb  = (const float*)d_in[3];
    const float* Wk  = (const float*)d_in[4];
    const float* Wkb = (const float*)d_in[5];
    const float* Wa  = (const float*)d_in[6];
    const float* Wab = (const float*)d_in[7];
    const float* Wb  = (const float*)d_in[8];
    const float* Wbb = (const float*)d_in[9];
    const float* enorm = (const float*)d_in[10];
    const int* user = (const int*)d_in[11];
    const int* pos  = (const int*)d_in[12];
    const int* neg  = (const int*)d_in[13];
    const int* eu   = (const int*)d_in[14];
    const int* ei   = (const int*)d_in[15];
    const int* kgr  = (const int*)d_in[16];
    const int* kge  = (const int*)d_in[17];

    void* p;
    cudaGetSymbolAddress(&p, g_aggu);
    float* aggu0 = (float*)p;
    float* aggu1 = aggu0 + (size_t)NU * DD;
    cudaGetSymbolAddress(&p, g_inext);
    float* in0 = (float*)p;
    float* in1 = in0 + (size_t)NI * DD;
    cudaGetSymbolAddress(&p, g_aggi);
    float* aggi = (float*)p;

    const int ATTN_WPB = 8;
    const int attn_grid = (NI + ATTN_WPB - 1) / ATTN_WPB;
    const int edge_grid = ((NEDGE / 2) * 16) / 256;  // 1M edge-pairs * 16 lanes / 256
    const int comb_grid = (NI + 63) / 64;

    for (int l = 0; l < NL; l++) {
        const float* ucur = (l == 0) ? user_emb : aggu0;
        const float* icur = (l == 0) ? item_emb : in0;
        float* aggu  = (l == 0) ? aggu0 : aggu1;
        float* inext = (l == 0) ? in0 : in1;

        cudaMemsetAsync(aggu, 0, (size_t)NU * DD * sizeof(float));
        cudaMemsetAsync(aggi, 0, (size_t)NI * DD * sizeof(float));

        rw_kernel<<<NR, DD>>>(rel_emb, Wk + (size_t)l * DD * 2 * DD, Wkb + (size_t)l * DD);
        attn_kernel<<<attn_grid, 32 * ATTN_WPB>>>(icur, ent_emb, kgr, kge);
        edge_kernel<<<edge_grid, 256>>>(ucur, icur, eu, ei, enorm, aggu, aggi);
        combine_kernel<<<comb_grid, 256>>>(Wa + (size_t)l * DD * DD, Wab + (size_t)l * DD,
                                           Wb + (size_t)l * DD * DD, Wbb + (size_t)l * DD, inext);
    }

    zero_acc_kernel<<<1, 1>>>();
    loss_kernel<<<NB / 8, 256>>>(user_emb, item_emb, aggu0, aggu1, in0, in1, user, pos, neg);
    final_kernel<<<1, 1>>>((float*)d_out);
}

// round 5
// speedup vs baseline: 1.1898x; 1.1898x over previous
#include <cuda_runtime.h>
#include <cuda_bf16.h>
#include <math.h>

#define NU 100000
#define NI 50000
#define NE 200000
#define NR 64
#define DD 64
#define KK 16
#define NEDGE 2000000
#define NL 2
#define NB 4096
#define REG 1.0e-4f

// ---------------- scratch (static device globals; no allocation) ----------------
__device__ float g_aggu[2][NU * DD];   // agg_u per layer (becomes next u_cur; needed for u_sum)
__device__ float g_inext[2][NI * DD];  // i_cur after each layer (needed for i_sum)
__device__ float g_aggi[NI * DD];      // agg_i, reused per layer
__device__ float g_kg[NI * DD];        // kg_item, reused per layer
__device__ float g_rW[NR * DD];        // rel_emb @ W_eff (per layer, recomputed)
__device__ float g_rb[NR];             // rel_emb . Wk_b
__device__ double g_acc[2];            // [0]=sum log(sigmoid+eps), [1]=sum l2

// ---------------- vector red helper ----------------
__device__ __forceinline__ void red_add_v4(float* p, float a, float b, float c, float d) {
    asm volatile("red.global.add.v4.f32 [%0], {%1,%2,%3,%4};"
                 :: "l"(p), "f"(a), "f"(b), "f"(c), "f"(d) : "memory");
}

// ---------------- 1) per-layer relation projection: rW[n,d] = sum_o rel[n,o]*(Wk[o,d]+Wk[o,D+d]) ----
__global__ void rw_kernel(const float* __restrict__ rel, const float* __restrict__ Wk,
                          const float* __restrict__ Wkb) {
    int n = blockIdx.x;
    int d = threadIdx.x;
    float s = 0.f;
    #pragma unroll 8
    for (int o = 0; o < DD; o++) {
        float rv = __ldg(&rel[n * DD + o]);
        s += rv * (__ldg(&Wk[o * 2 * DD + d]) + __ldg(&Wk[o * 2 * DD + DD + d]));
    }
    g_rW[n * DD + d] = s;
    if (d == 0) {
        float t = 0.f;
        for (int o = 0; o < DD; o++) t += __ldg(&rel[n * DD + o]) * __ldg(&Wkb[o]);
        g_rb[n] = t;
    }
}

// ---------------- 2) KG attention: warp per item ----------------
__global__ void attn_kernel(const float* __restrict__ icur, const float* __restrict__ ent,
                            const int* __restrict__ kgr, const int* __restrict__ kge) {
    __shared__ float srW[NR * DD];
    __shared__ float srb[NR];
    for (int t = threadIdx.x; t < NR * DD; t += blockDim.x) srW[t] = g_rW[t];
    if (threadIdx.x < NR) srb[threadIdx.x] = g_rb[threadIdx.x];
    __syncthreads();

    int warp = threadIdx.x >> 5, lane = threadIdx.x & 31;
    int i = blockIdx.x * (blockDim.x >> 5) + warp;
    if (i >= NI) return;

    float2 ic = *(const float2*)&icur[i * DD + lane * 2];
    float sc[KK];
    float2 vv[KK];
    #pragma unroll
    for (int k = 0; k < KK; k++) {
        int e  = __ldg(&kge[i * KK + k]);
        int rn = __ldg(&kgr[i * KK + k]);
        float2 v = *(const float2*)&ent[(size_t)e * DD + lane * 2];
        vv[k] = v;
        float p = srW[rn * DD + lane * 2] * v.x * ic.x + srW[rn * DD + lane * 2 + 1] * v.y * ic.y;
        #pragma unroll
        for (int off = 16; off; off >>= 1) p += __shfl_xor_sync(0xffffffffu, p, off);
        p += srb[rn];
        sc[k] = (p > 0.f) ? p : 0.2f * p;  // leaky_relu(0.2)
    }
    // softmax over K (identical in all lanes)
    float m = sc[0];
    #pragma unroll
    for (int k = 1; k < KK; k++) m = fmaxf(m, sc[k]);
    float den = 0.f;
    #pragma unroll
    for (int k = 0; k < KK; k++) { sc[k] = __expf(sc[k] - m); den += sc[k]; }
    float inv = 1.f / den;
    float2 acc = make_float2(0.f, 0.f);
    #pragma unroll
    for (int k = 0; k < KK; k++) { acc.x += sc[k] * vv[k].x; acc.y += sc[k] * vv[k].y; }
    *(float2*)&g_kg[i * DD + lane * 2] = make_float2(acc.x * inv, acc.y * inv);
}

// ---------------- 3) edge aggregation: 2 edges/thread, 16 threads/edge-chunk, float4 + red.v4 ----
__global__ void edge_kernel(const float* __restrict__ ucur, const float* __restrict__ icur,
                            const int* __restrict__ eu, const int* __restrict__ ei,
                            const float* __restrict__ nw,
                            float* __restrict__ aggu, float* __restrict__ aggi) {
    const int HALF = NEDGE / 2;
    int gid = blockIdx.x * blockDim.x + threadIdx.x;
    int e0 = gid >> 4;
    int c = (gid & 15) * 4;
    if (e0 >= HALF) return;
    int e1 = e0 + HALF;

    // front-batch all index/weight/gather loads for both edges (MLP_eff ~ 2x)
    int u0  = __ldg(&eu[e0]);
    int i0  = __ldg(&ei[e0]);
    int u1  = __ldg(&eu[e1]);
    int i1  = __ldg(&ei[e1]);
    float n0 = __ldg(&nw[e0]);
    float n1 = __ldg(&nw[e1]);

    float4 uv0 = __ldg((const float4*)&ucur[u0 * DD + c]);
    float4 iv0 = __ldg((const float4*)&icur[i0 * DD + c]);
    float4 uv1 = __ldg((const float4*)&ucur[u1 * DD + c]);
    float4 iv1 = __ldg((const float4*)&icur[i1 * DD + c]);

    red_add_v4(&aggi[i0 * DD + c], n0 * uv0.x, n0 * uv0.y, n0 * uv0.z, n0 * uv0.w);
    red_add_v4(&aggu[u0 * DD + c], n0 * iv0.x, n0 * iv0.y, n0 * iv0.z, n0 * iv0.w);
    red_add_v4(&aggi[i1 * DD + c], n1 * uv1.x, n1 * uv1.y, n1 * uv1.z, n1 * uv1.w);
    red_add_v4(&aggu[u1 * DD + c], n1 * iv1.x, n1 * iv1.y, n1 * iv1.z, n1 * iv1.w);
}

// ---------------- 4) gate + combine: register-blocked 4x4 dual-GEMM ----------------
// SWIZ: float4-granular index into a 64x64 tile stored as 64 rows x 16 float4,
// column swizzled by row so row starts spread across all 8 quad-banks.
#define SWIZ(r, c4) (((r) << 4) + (((c4) ^ ((r) & 7))))

__global__ __launch_bounds__(256, 2)
void combine_kernel(const float* __restrict__ Wa, const float* __restrict__ Wab,
                    const float* __restrict__ Wb, const float* __restrict__ Wbb,
                    float* __restrict__ out) {
    extern __shared__ float sm[];
    float4* sWa = (float4*)sm;            // 1024 float4 (64x64)
    float4* sWb = sWa + 1024;
    float4* sKg = sWb + 1024;
    float4* sAg = sKg + 1024;
    float*  sab = (float*)(sAg + 1024);   // 64
    float*  sbb = sab + 64;               // 64

    int tid = threadIdx.x;
    int item0 = blockIdx.x * 64;

    for (int i = tid; i < 1024; i += 256) {
        int r = i >> 4, c4 = i & 15;
        float4 a = __ldg((const float4*)&Wa[r * DD + c4 * 4]);
        float4 b = __ldg((const float4*)&Wb[r * DD + c4 * 4]);
        sWa[SWIZ(r, c4)] = a;
        sWb[SWIZ(r, c4)] = b;
        int item = item0 + r;
        float4 k = make_float4(0.f, 0.f, 0.f, 0.f);
        float4 g = make_float4(0.f, 0.f, 0.f, 0.f);
        if (item < NI) {
            k = *(const float4*)&g_kg[item * DD + c4 * 4];
            g = *(const float4*)&g_aggi[item * DD + c4 * 4];
        }
        sKg[SWIZ(r, c4)] = k;
        sAg[SWIZ(r, c4)] = g;
    }
    if (tid < DD) { sab[tid] = __ldg(&Wab[tid]); sbb[tid] = __ldg(&Wbb[tid]); }
    __syncthreads();

    // thread owns outputs o = to + 16*oi, items j = tj + 16*ji  (strided blocking)
    int to = tid & 15, tj = tid >> 4;
    float accA[4][4], accB[4][4];
    #pragma unroll
    for (int a = 0; a < 4; a++)
        #pragma unroll
        for (int b = 0; b < 4; b++) { accA[a][b] = 0.f; accB[a][b] = 0.f; }

    #pragma unroll
    for (int d4 = 0; d4 < 16; d4++) {
        float4 wa[4], wb[4], kg[4], ag[4];
        #pragma unroll
        for (int x = 0; x < 4; x++) {
            wa[x] = sWa[SWIZ(to + 16 * x, d4)];
            wb[x] = sWb[SWIZ(to + 16 * x, d4)];
            kg[x] = sKg[SWIZ(tj + 16 * x, d4)];
            ag[x] = sAg[SWIZ(tj + 16 * x, d4)];
        }
        #pragma unroll
        for (int oi = 0; oi < 4; oi++)
            #pragma unroll
            for (int ji = 0; ji < 4; ji++) {
                accA[oi][ji] += wa[oi].x * kg[ji].x + wa[oi].y * kg[ji].y
                              + wa[oi].z * kg[ji].z + wa[oi].w * kg[ji].w;
                accB[oi][ji] += wb[oi].x * ag[ji].x + wb[oi].y * ag[ji].y
                              + wb[oi].z * ag[ji].z + wb[oi].w * ag[ji].w;
            }
    }

    const float* sKgf = (const float*)sKg;
    const float* sAgf = (const float*)sAg;
    #pragma unroll
    for (int ji = 0; ji < 4; ji++) {
        int j = tj + 16 * ji;
        int item = item0 + j;
        if (item < NI) {
            #pragma unroll
            for (int oi = 0; oi < 4; oi++) {
                int o = to + 16 * oi;
                float kv = sKgf[SWIZ(j, o >> 2) * 4 + (o & 3)];
                float av = sAgf[SWIZ(j, o >> 2) * 4 + (o & 3)];
                float z = accA[oi][ji] + sab[o] + accB[oi][ji] + sbb[o];
                float gate = 1.f / (1.f + __expf(-z));
                out[item * DD + o] = gate * kv + (1.f - gate) * av;
            }
        }
    }
}

// ---------------- 5) loss reduction ----------------
__global__ void zero_acc_kernel() { g_acc[0] = 0.0; g_acc[1] = 0.0; }

__global__ void loss_kernel(const float* __restrict__ uemb, const float* __restrict__ iemb,
                            const float* __restrict__ U0, const float* __restrict__ U1,
                            const float* __restrict__ I0, const float* __restrict__ I1,
                            const int* __restrict__ user, const int* __restrict__ pos,
                            const int* __restrict__ neg) {
    int warp = (blockIdx.x * blockDim.x + threadIdx.x) >> 5;
    int lane = threadIdx.x & 31;
    if (warp >= NB) return;
    int u = __ldg(&user[warp]), p = __ldg(&pos[warp]), n = __ldg(&neg[warp]);
    int du = u * DD + lane * 2, dp = p * DD + lane * 2, dn = n * DD + lane * 2;

    float2 a = *(const float2*)&uemb[du];
    float2 b = *(const float2*)&U0[du];
    float2 c = *(const float2*)&U1[du];
    float2 ue = make_float2(a.x + b.x + c.x, a.y + b.y + c.y);

    a = *(const float2*)&iemb[dp]; b = *(const float2*)&I0[dp]; c = *(const float2*)&I1[dp];
    float2 pe = make_float2(a.x + b.x + c.x, a.y + b.y + c.y);

    a = *(const float2*)&iemb[dn]; b = *(const float2*)&I0[dn]; c = *(const float2*)&I1[dn];
    float2 ne = make_float2(a.x + b.x + c.x, a.y + b.y + c.y);

    float ps = ue.x * pe.x + ue.y * pe.y;
    float ns = ue.x * ne.x + ue.y * ne.y;
    float l2 = ue.x * ue.x + ue.y * ue.y + pe.x * pe.x + pe.y * pe.y + ne.x * ne.x + ne.y * ne.y;
    #pragma unroll
    for (int off = 16; off; off >>= 1) {
        ps += __shfl_xor_sync(0xffffffffu, ps, off);
        ns += __shfl_xor_sync(0xffffffffu, ns, off);
        l2 += __shfl_xor_sync(0xffffffffu, l2, off);
    }
    if (lane == 0) {
        float diff = ps - ns;
        float sig = 1.f / (1.f + expf(-diff));
        atomicAdd(&g_acc[0], (double)logf(sig + 1e-10f));
        atomicAdd(&g_acc[1], (double)l2);
    }
}

__global__ void final_kernel(float* __restrict__ out) {
    double bpr = -g_acc[0] / (double)NB;
    double l2  = g_acc[1] / (double)NB;
    out[0] = (float)(bpr + (double)REG * l2);
}

// ---------------- host ----------------
extern "C" void kernel_launch(void* const* d_in, const int* in_sizes, int n_in,
                              void* d_out, int out_size) {
    const float* user_emb = (const float*)d_in[0];
    const float* item_emb = (const float*)d_in[1];
    const float* ent_emb  = (const float*)d_in[2];
    const float* rel_emb  = (const float*)d_in[3];
    const float* Wk  = (const float*)d_in[4];
    const float* Wkb = (const float*)d_in[5];
    const float* Wa  = (const float*)d_in[6];
    const float* Wab = (const float*)d_in[7];
    const float* Wb  = (const float*)d_in[8];
    const float* Wbb = (const float*)d_in[9];
    const float* enorm = (const float*)d_in[10];
    const int* user = (const int*)d_in[11];
    const int* pos  = (const int*)d_in[12];
    const int* neg  = (const int*)d_in[13];
    const int* eu   = (const int*)d_in[14];
    const int* ei   = (const int*)d_in[15];
    const int* kgr  = (const int*)d_in[16];
    const int* kge  = (const int*)d_in[17];

    void* p;
    cudaGetSymbolAddress(&p, g_aggu);
    float* aggu0 = (float*)p;
    float* aggu1 = aggu0 + (size_t)NU * DD;
    cudaGetSymbolAddress(&p, g_inext);
    float* in0 = (float*)p;
    float* in1 = in0 + (size_t)NI * DD;
    cudaGetSymbolAddress(&p, g_aggi);
    float* aggi = (float*)p;

    const int ATTN_WPB = 8;
    const int attn_grid = (NI + ATTN_WPB - 1) / ATTN_WPB;
    const int edge_grid = ((NEDGE / 2) * 16) / 256;  // 1M edge-pairs * 16 lanes / 256
    const int comb_grid = (NI + 63) / 64;
    const int comb_smem = 4096 * 16 + 128 * 4;       // 64.5 KB dynamic

    cudaFuncSetAttribute(combine_kernel, cudaFuncAttributeMaxDynamicSharedMemorySize, comb_smem);

    for (int l = 0; l < NL; l++) {
        const float* ucur = (l == 0) ? user_emb : aggu0;
        const float* icur = (l == 0) ? item_emb : in0;
        float* aggu  = (l == 0) ? aggu0 : aggu1;
        float* inext = (l == 0) ? in0 : in1;

        cudaMemsetAsync(aggu, 0, (size_t)NU * DD * sizeof(float));
        cudaMemsetAsync(aggi, 0, (size_t)NI * DD * sizeof(float));

        rw_kernel<<<NR, DD>>>(rel_emb, Wk + (size_t)l * DD * 2 * DD, Wkb + (size_t)l * DD);
        attn_kernel<<<attn_grid, 32 * ATTN_WPB>>>(icur, ent_emb, kgr, kge);
        edge_kernel<<<edge_grid, 256>>>(ucur, icur, eu, ei, enorm, aggu, aggi);
        combine_kernel<<<comb_grid, 256, comb_smem>>>(Wa + (size_t)l * DD * DD, Wab + (size_t)l * DD,
                                                      Wb + (size_t)l * DD * DD, Wbb + (size_t)l * DD, inext);
    }

    zero_acc_kernel<<<1, 1>>>();
    loss_kernel<<<NB / 8, 256>>>(user_emb, item_emb, aggu0, aggu1, in0, in1, user, pos, neg);
    final_kernel<<<1, 1>>>((float*)d_out);
}

// round 6
// speedup vs baseline: 1.1949x; 1.0043x over previous
#include <cuda_runtime.h>
#include <cuda_bf16.h>
#include <math.h>

#define NU 100000
#define NI 50000
#define NE 200000
#define NR 64
#define DD 64
#define KK 16
#define NEDGE 2000000
#define NL 2
#define NB 4096
#define REG 1.0e-4f

// ---------------- scratch (static device globals; no allocation) ----------------
__device__ float g_aggu[2][NU * DD];   // agg_u per layer (becomes next u_cur; needed for u_sum)
__device__ float g_inext[2][NI * DD];  // i_cur after each layer (needed for i_sum)
__device__ float g_aggi[NI * DD];      // agg_i, reused per layer
__device__ float g_kg[NI * DD];        // kg_item, reused per layer
__device__ float g_rW[NR * DD];        // rel_emb @ W_eff (per layer, recomputed)
__device__ float g_rb[NR];             // rel_emb . Wk_b
__device__ double g_acc[2];            // [0]=sum log(sigmoid+eps), [1]=sum l2

// ---------------- vector red helper ----------------
__device__ __forceinline__ void red_add_v4(float* p, float a, float b, float c, float d) {
    asm volatile("red.global.add.v4.f32 [%0], {%1,%2,%3,%4};"
                 :: "l"(p), "f"(a), "f"(b), "f"(c), "f"(d) : "memory");
}

// ---------------- 1) per-layer relation projection: rW[n,d] = sum_o rel[n,o]*(Wk[o,d]+Wk[o,D+d]) ----
__global__ void rw_kernel(const float* __restrict__ rel, const float* __restrict__ Wk,
                          const float* __restrict__ Wkb) {
    int n = blockIdx.x;
    int d = threadIdx.x;
    float s = 0.f;
    #pragma unroll 8
    for (int o = 0; o < DD; o++) {
        float rv = __ldg(&rel[n * DD + o]);
        s += rv * (__ldg(&Wk[o * 2 * DD + d]) + __ldg(&Wk[o * 2 * DD + DD + d]));
    }
    g_rW[n * DD + d] = s;
    if (d == 0) {
        float t = 0.f;
        for (int o = 0; o < DD; o++) t += __ldg(&rel[n * DD + o]) * __ldg(&Wkb[o]);
        g_rb[n] = t;
    }
}

// ---------------- 2) KG attention: warp per item ----------------
__global__ void attn_kernel(const float* __restrict__ icur, const float* __restrict__ ent,
                            const int* __restrict__ kgr, const int* __restrict__ kge) {
    __shared__ float srW[NR * DD];
    __shared__ float srb[NR];
    for (int t = threadIdx.x; t < NR * DD; t += blockDim.x) srW[t] = g_rW[t];
    if (threadIdx.x < NR) srb[threadIdx.x] = g_rb[threadIdx.x];
    __syncthreads();

    int warp = threadIdx.x >> 5, lane = threadIdx.x & 31;
    int i = blockIdx.x * (blockDim.x >> 5) + warp;
    if (i >= NI) return;

    float2 ic = *(const float2*)&icur[i * DD + lane * 2];
    float sc[KK];
    float2 vv[KK];
    #pragma unroll
    for (int k = 0; k < KK; k++) {
        int e  = __ldg(&kge[i * KK + k]);
        int rn = __ldg(&kgr[i * KK + k]);
        float2 v = *(const float2*)&ent[(size_t)e * DD + lane * 2];
        vv[k] = v;
        float p = srW[rn * DD + lane * 2] * v.x * ic.x + srW[rn * DD + lane * 2 + 1] * v.y * ic.y;
        #pragma unroll
        for (int off = 16; off; off >>= 1) p += __shfl_xor_sync(0xffffffffu, p, off);
        p += srb[rn];
        sc[k] = (p > 0.f) ? p : 0.2f * p;  // leaky_relu(0.2)
    }
    // softmax over K (identical in all lanes)
    float m = sc[0];
    #pragma unroll
    for (int k = 1; k < KK; k++) m = fmaxf(m, sc[k]);
    float den = 0.f;
    #pragma unroll
    for (int k = 0; k < KK; k++) { sc[k] = __expf(sc[k] - m); den += sc[k]; }
    float inv = 1.f / den;
    float2 acc = make_float2(0.f, 0.f);
    #pragma unroll
    for (int k = 0; k < KK; k++) { acc.x += sc[k] * vv[k].x; acc.y += sc[k] * vv[k].y; }
    *(float2*)&g_kg[i * DD + lane * 2] = make_float2(acc.x * inv, acc.y * inv);
}

// ---------------- 3) edge aggregation: 4 edges/thread, 16 threads/edge-chunk, float4 + red.v4 ----
__global__ void edge_kernel(const float* __restrict__ ucur, const float* __restrict__ icur,
                            const int* __restrict__ eu, const int* __restrict__ ei,
                            const float* __restrict__ nw,
                            float* __restrict__ aggu, float* __restrict__ aggi) {
    const int Q = NEDGE / 4;
    int gid = blockIdx.x * blockDim.x + threadIdx.x;
    int e0 = gid >> 4;
    int c = (gid & 15) * 4;
    if (e0 >= Q) return;

    int u[4], it[4];
    float n[4];
    #pragma unroll
    for (int x = 0; x < 4; x++) {
        int e = e0 + x * Q;
        u[x]  = __ldg(&eu[e]);
        it[x] = __ldg(&ei[e]);
        n[x]  = __ldg(&nw[e]);
    }
    float4 uv[4], iv[4];
    #pragma unroll
    for (int x = 0; x < 4; x++) {
        uv[x] = __ldg((const float4*)&ucur[u[x] * DD + c]);
        iv[x] = __ldg((const float4*)&icur[it[x] * DD + c]);
    }
    #pragma unroll
    for (int x = 0; x < 4; x++) {
        red_add_v4(&aggi[it[x] * DD + c], n[x] * uv[x].x, n[x] * uv[x].y, n[x] * uv[x].z, n[x] * uv[x].w);
        red_add_v4(&aggu[u[x] * DD + c],  n[x] * iv[x].x, n[x] * iv[x].y, n[x] * iv[x].z, n[x] * iv[x].w);
    }
}

// ---------------- 4) gate + combine: register-blocked 4x4 dual-GEMM ----------------
// SWIZ: float4-granular index into a 64x64 tile stored as 64 rows x 16 float4,
// column swizzled by row so row starts spread across all 8 quad-banks.
#define SWIZ(r, c4) (((r) << 4) + (((c4) ^ ((r) & 7))))

__global__ __launch_bounds__(256, 2)
void combine_kernel(const float* __restrict__ Wa, const float* __restrict__ Wab,
                    const float* __restrict__ Wb, const float* __restrict__ Wbb,
                    float* __restrict__ out) {
    extern __shared__ float sm[];
    float4* sWa = (float4*)sm;            // 1024 float4 (64x64)
    float4* sWb = sWa + 1024;
    float4* sKg = sWb + 1024;
    float4* sAg = sKg + 1024;
    float*  sab = (float*)(sAg + 1024);   // 64
    float*  sbb = sab + 64;               // 64

    int tid = threadIdx.x;
    int item0 = blockIdx.x * 64;

    for (int i = tid; i < 1024; i += 256) {
        int r = i >> 4, c4 = i & 15;
        float4 a = __ldg((const float4*)&Wa[r * DD + c4 * 4]);
        float4 b = __ldg((const float4*)&Wb[r * DD + c4 * 4]);
        sWa[SWIZ(r, c4)] = a;
        sWb[SWIZ(r, c4)] = b;
        int item = item0 + r;
        float4 k = make_float4(0.f, 0.f, 0.f, 0.f);
        float4 g = make_float4(0.f, 0.f, 0.f, 0.f);
        if (item < NI) {
            k = *(const float4*)&g_kg[item * DD + c4 * 4];
            g = *(const float4*)&g_aggi[item * DD + c4 * 4];
        }
        sKg[SWIZ(r, c4)] = k;
        sAg[SWIZ(r, c4)] = g;
    }
    if (tid < DD) { sab[tid] = __ldg(&Wab[tid]); sbb[tid] = __ldg(&Wbb[tid]); }
    __syncthreads();

    // thread owns outputs o = to + 16*oi, items j = tj + 16*ji  (strided blocking)
    int to = tid & 15, tj = tid >> 4;
    float accA[4][4], accB[4][4];
    #pragma unroll
    for (int a = 0; a < 4; a++)
        #pragma unroll
        for (int b = 0; b < 4; b++) { accA[a][b] = 0.f; accB[a][b] = 0.f; }

    #pragma unroll
    for (int d4 = 0; d4 < 16; d4++) {
        float4 wa[4], wb[4], kg[4], ag[4];
        #pragma unroll
        for (int x = 0; x < 4; x++) {
            wa[x] = sWa[SWIZ(to + 16 * x, d4)];
            wb[x] = sWb[SWIZ(to + 16 * x, d4)];
            kg[x] = sKg[SWIZ(tj + 16 * x, d4)];
            ag[x] = sAg[SWIZ(tj + 16 * x, d4)];
        }
        #pragma unroll
        for (int oi = 0; oi < 4; oi++)
            #pragma unroll
            for (int ji = 0; ji < 4; ji++) {
                accA[oi][ji] += wa[oi].x * kg[ji].x + wa[oi].y * kg[ji].y
                              + wa[oi].z * kg[ji].z + wa[oi].w * kg[ji].w;
                accB[oi][ji] += wb[oi].x * ag[ji].x + wb[oi].y * ag[ji].y
                              + wb[oi].z * ag[ji].z + wb[oi].w * ag[ji].w;
            }
    }

    const float* sKgf = (const float*)sKg;
    const float* sAgf = (const float*)sAg;
    #pragma unroll
    for (int ji = 0; ji < 4; ji++) {
        int j = tj + 16 * ji;
        int item = item0 + j;
        if (item < NI) {
            #pragma unroll
            for (int oi = 0; oi < 4; oi++) {
                int o = to + 16 * oi;
                float kv = sKgf[SWIZ(j, o >> 2) * 4 + (o & 3)];
                float av = sAgf[SWIZ(j, o >> 2) * 4 + (o & 3)];
                float z = accA[oi][ji] + sab[o] + accB[oi][ji] + sbb[o];
                float gate = 1.f / (1.f + __expf(-z));
                out[item * DD + o] = gate * kv + (1.f - gate) * av;
            }
        }
    }
}

// ---------------- 5) loss reduction ----------------
__global__ void zero_acc_kernel() { g_acc[0] = 0.0; g_acc[1] = 0.0; }

__global__ void loss_kernel(const float* __restrict__ uemb, const float* __restrict__ iemb,
                            const float* __restrict__ U0, const float* __restrict__ U1,
                            const float* __restrict__ I0, const float* __restrict__ I1,
                            const int* __restrict__ user, const int* __restrict__ pos,
                            const int* __restrict__ neg) {
    int warp = (blockIdx.x * blockDim.x + threadIdx.x) >> 5;
    int lane = threadIdx.x & 31;
    if (warp >= NB) return;
    int u = __ldg(&user[warp]), p = __ldg(&pos[warp]), n = __ldg(&neg[warp]);
    int du = u * DD + lane * 2, dp = p * DD + lane * 2, dn = n * DD + lane * 2;

    float2 a = *(const float2*)&uemb[du];
    float2 b = *(const float2*)&U0[du];
    float2 c = *(const float2*)&U1[du];
    float2 ue = make_float2(a.x + b.x + c.x, a.y + b.y + c.y);

    a = *(const float2*)&iemb[dp]; b = *(const float2*)&I0[dp]; c = *(const float2*)&I1[dp];
    float2 pe = make_float2(a.x + b.x + c.x, a.y + b.y + c.y);

    a = *(const float2*)&iemb[dn]; b = *(const float2*)&I0[dn]; c = *(const float2*)&I1[dn];
    float2 ne = make_float2(a.x + b.x + c.x, a.y + b.y + c.y);

    float ps = ue.x * pe.x + ue.y * pe.y;
    float ns = ue.x * ne.x + ue.y * ne.y;
    float l2 = ue.x * ue.x + ue.y * ue.y + pe.x * pe.x + pe.y * pe.y + ne.x * ne.x + ne.y * ne.y;
    #pragma unroll
    for (int off = 16; off; off >>= 1) {
        ps += __shfl_xor_sync(0xffffffffu, ps, off);
        ns += __shfl_xor_sync(0xffffffffu, ns, off);
        l2 += __shfl_xor_sync(0xffffffffu, l2, off);
    }
    if (lane == 0) {
        float diff = ps - ns;
        float sig = 1.f / (1.f + expf(-diff));
        atomicAdd(&g_acc[0], (double)logf(sig + 1e-10f));
        atomicAdd(&g_acc[1], (double)l2);
    }
}

__global__ void final_kernel(float* __restrict__ out) {
    double bpr = -g_acc[0] / (double)NB;
    double l2  = g_acc[1] / (double)NB;
    out[0] = (float)(bpr + (double)REG * l2);
}

// ---------------- host ----------------
extern "C" void kernel_launch(void* const* d_in, const int* in_sizes, int n_in,
                              void* d_out, int out_size) {
    const float* user_emb = (const float*)d_in[0];
    const float* item_emb = (const float*)d_in[1];
    const float* ent_emb  = (const float*)d_in[2];
    const float* rel_emb  = (const float*)d_in[3];
    const float* Wk  = (const float*)d_in[4];
    const float* Wkb = (const float*)d_in[5];
    const float* Wa  = (const float*)d_in[6];
    const float* Wab = (const float*)d_in[7];
    const float* Wb  = (const float*)d_in[8];
    const float* Wbb = (const float*)d_in[9];
    const float* enorm = (const float*)d_in[10];
    const int* user = (const int*)d_in[11];
    const int* pos  = (const int*)d_in[12];
    const int* neg  = (const int*)d_in[13];
    const int* eu   = (const int*)d_in[14];
    const int* ei   = (const int*)d_in[15];
    const int* kgr  = (const int*)d_in[16];
    const int* kge  = (const int*)d_in[17];

    void* p;
    cudaGetSymbolAddress(&p, g_aggu);
    float* aggu0 = (float*)p;
    float* aggu1 = aggu0 + (size_t)NU * DD;
    cudaGetSymbolAddress(&p, g_inext);
    float* in0 = (float*)p;
    float* in1 = in0 + (size_t)NI * DD;
    cudaGetSymbolAddress(&p, g_aggi);
    float* aggi = (float*)p;

    const int ATTN_WPB = 8;
    const int attn_grid = (NI + ATTN_WPB - 1) / ATTN_WPB;
    const int edge_grid = ((NEDGE / 4) * 16) / 256;  // 500K edge-quads * 16 lanes / 256
    const int comb_grid = (NI + 63) / 64;
    const int comb_smem = 4096 * 16 + 128 * 4;       // 64.5 KB dynamic

    cudaFuncSetAttribute(combine_kernel, cudaFuncAttributeMaxDynamicSharedMemorySize, comb_smem);

    // launch #1 so that edge_kernel of layer 0 is launch #6 (ncu -s 5 -c 1 captures it)
    zero_acc_kernel<<<1, 1>>>();

    for (int l = 0; l < NL; l++) {
        const float* ucur = (l == 0) ? user_emb : aggu0;
        const float* icur = (l == 0) ? item_emb : in0;
        float* aggu  = (l == 0) ? aggu0 : aggu1;
        float* inext = (l == 0) ? in0 : in1;

        rw_kernel<<<NR, DD>>>(rel_emb, Wk + (size_t)l * DD * 2 * DD, Wkb + (size_t)l * DD);
        attn_kernel<<<attn_grid, 32 * ATTN_WPB>>>(icur, ent_emb, kgr, kge);
        cudaMemsetAsync(aggu, 0, (size_t)NU * DD * sizeof(float));
        cudaMemsetAsync(aggi, 0, (size_t)NI * DD * sizeof(float));
        edge_kernel<<<edge_grid, 256>>>(ucur, icur, eu, ei, enorm, aggu, aggi);
        combine_kernel<<<comb_grid, 256, comb_smem>>>(Wa + (size_t)l * DD * DD, Wab + (size_t)l * DD,
                                                      Wb + (size_t)l * DD * DD, Wbb + (size_t)l * DD, inext);
    }

    loss_kernel<<<NB / 8, 256>>>(user_emb, item_emb, aggu0, aggu1, in0, in1, user, pos, neg);
    final_kernel<<<1, 1>>>((float*)d_out);
}

// round 17
// speedup vs baseline: 1.2221x; 1.0227x over previous
#include <cuda_runtime.h>
#include <cuda_bf16.h>
#include <math.h>

#define NU 100000
#define NI 50000
#define NE 200000
#define NR 64
#define DD 64
#define KK 16
#define NEDGE 2000000
#define NL 2
#define NB 4096
#define REG 1.0e-4f

// ---------------- scratch (static device globals; no allocation) ----------------
__device__ float g_aggu[2][NU * DD];   // agg_u per layer (becomes next u_cur; needed for u_sum)
__device__ float g_inext[2][NI * DD];  // i_cur after each layer (needed for i_sum)
__device__ float g_aggi[NI * DD];      // agg_i, reused per layer
__device__ float g_kg[NI * DD];        // kg_item, reused per layer
__device__ float g_rW[NR * DD];        // rel_emb @ W_eff (per layer, recomputed)
__device__ float g_rb[NR];             // rel_emb . Wk_b
__device__ double g_acc[2];            // [0]=sum log(sigmoid+eps), [1]=sum l2
__device__ __nv_bfloat16 g_ub[NU * DD];  // bf16 copy of current user table (edge gathers)
__device__ __nv_bfloat16 g_ib[NI * DD];  // bf16 copy of current item table (edge gathers)

// ---------------- vector red helper ----------------
__device__ __forceinline__ void red_add_v4(float* p, float a, float b, float c, float d) {
    asm volatile("red.global.add.v4.f32 [%0], {%1,%2,%3,%4};"
                 :: "l"(p), "f"(a), "f"(b), "f"(c), "f"(d) : "memory");
}

// ---------------- 0) fp32 -> bf16 table conversion ----------------
__global__ void tobf16_kernel(const float* __restrict__ src, __nv_bfloat16* __restrict__ dst, int n4) {
    int i = blockIdx.x * blockDim.x + threadIdx.x;
    if (i >= n4) return;
    float4 v = __ldg((const float4*)&src[i * 4]);
    __nv_bfloat162 a = __floats2bfloat162_rn(v.x, v.y);
    __nv_bfloat162 b = __floats2bfloat162_rn(v.z, v.w);
    uint2 o;
    o.x = *(unsigned*)&a;
    o.y = *(unsigned*)&b;
    *(uint2*)&dst[i * 4] = o;
}

// ---------------- 1) per-layer relation projection: rW[n,d] = sum_o rel[n,o]*(Wk[o,d]+Wk[o,D+d]) ----
__global__ void rw_kernel(const float* __restrict__ rel, const float* __restrict__ Wk,
                          const float* __restrict__ Wkb) {
    int n = blockIdx.x;
    int d = threadIdx.x;
    float s = 0.f;
    #pragma unroll 8
    for (int o = 0; o < DD; o++) {
        float rv = __ldg(&rel[n * DD + o]);
        s += rv * (__ldg(&Wk[o * 2 * DD + d]) + __ldg(&Wk[o * 2 * DD + DD + d]));
    }
    g_rW[n * DD + d] = s;
    if (d == 0) {
        float t = 0.f;
        for (int o = 0; o < DD; o++) t += __ldg(&rel[n * DD + o]) * __ldg(&Wkb[o]);
        g_rb[n] = t;
    }
}

// ---------------- 2) KG attention: warp per item (fp32 throughout) ----------------
__global__ void attn_kernel(const float* __restrict__ icur, const float* __restrict__ ent,
                            const int* __restrict__ kgr, const int* __restrict__ kge) {
    __shared__ float srW[NR * DD];
    __shared__ float srb[NR];
    for (int t = threadIdx.x; t < NR * DD; t += blockDim.x) srW[t] = g_rW[t];
    if (threadIdx.x < NR) srb[threadIdx.x] = g_rb[threadIdx.x];
    __syncthreads();

    int warp = threadIdx.x >> 5, lane = threadIdx.x & 31;
    int i = blockIdx.x * (blockDim.x >> 5) + warp;
    if (i >= NI) return;

    float2 ic = *(const float2*)&icur[i * DD + lane * 2];
    float sc[KK];
    float2 vv[KK];
    #pragma unroll
    for (int k = 0; k < KK; k++) {
        int e  = __ldg(&kge[i * KK + k]);
        int rn = __ldg(&kgr[i * KK + k]);
        float2 v = *(const float2*)&ent[(size_t)e * DD + lane * 2];
        vv[k] = v;
        float p = srW[rn * DD + lane * 2] * v.x * ic.x + srW[rn * DD + lane * 2 + 1] * v.y * ic.y;
        #pragma unroll
        for (int off = 16; off; off >>= 1) p += __shfl_xor_sync(0xffffffffu, p, off);
        p += srb[rn];
        sc[k] = (p > 0.f) ? p : 0.2f * p;  // leaky_relu(0.2)
    }
    // softmax over K (identical in all lanes)
    float m = sc[0];
    #pragma unroll
    for (int k = 1; k < KK; k++) m = fmaxf(m, sc[k]);
    float den = 0.f;
    #pragma unroll
    for (int k = 0; k < KK; k++) { sc[k] = __expf(sc[k] - m); den += sc[k]; }
    float inv = 1.f / den;
    float2 acc = make_float2(0.f, 0.f);
    #pragma unroll
    for (int k = 0; k < KK; k++) { acc.x += sc[k] * vv[k].x; acc.y += sc[k] * vv[k].y; }
    *(float2*)&g_kg[i * DD + lane * 2] = make_float2(acc.x * inv, acc.y * inv);
}

// ---------------- 3) edge aggregation: bf16 gathers, fp32 red.v4; 4 edges/thread ----------------
__device__ __forceinline__ float4 bf16x4_to_f4(uint2 r) {
    __nv_bfloat162 h0 = *(__nv_bfloat162*)&r.x;
    __nv_bfloat162 h1 = *(__nv_bfloat162*)&r.y;
    float2 f0 = __bfloat1622float2(h0);
    float2 f1 = __bfloat1622float2(h1);
    return make_float4(f0.x, f0.y, f1.x, f1.y);
}

__global__ void edge_kernel(const __nv_bfloat16* __restrict__ ub, const __nv_bfloat16* __restrict__ ib,
                            const int* __restrict__ eu, const int* __restrict__ ei,
                            const float* __restrict__ nw,
                            float* __restrict__ aggu, float* __restrict__ aggi) {
    const int Q = NEDGE / 4;
    int gid = blockIdx.x * blockDim.x + threadIdx.x;
    int e0 = gid >> 4;
    int c = (gid & 15) * 4;
    if (e0 >= Q) return;

    int u[4], it[4];
    float n[4];
    #pragma unroll
    for (int x = 0; x < 4; x++) {
        int e = e0 + x * Q;
        u[x]  = __ldg(&eu[e]);
        it[x] = __ldg(&ei[e]);
        n[x]  = __ldg(&nw[e]);
    }
    uint2 uraw[4], iraw[4];
    #pragma unroll
    for (int x = 0; x < 4; x++) {
        uraw[x] = __ldg((const uint2*)&ub[u[x] * DD + c]);
        iraw[x] = __ldg((const uint2*)&ib[it[x] * DD + c]);
    }
    #pragma unroll
    for (int x = 0; x < 4; x++) {
        float4 uv = bf16x4_to_f4(uraw[x]);
        float4 iv = bf16x4_to_f4(iraw[x]);
        red_add_v4(&aggi[it[x] * DD + c], n[x] * uv.x, n[x] * uv.y, n[x] * uv.z, n[x] * uv.w);
        red_add_v4(&aggu[u[x] * DD + c],  n[x] * iv.x, n[x] * iv.y, n[x] * iv.z, n[x] * iv.w);
    }
}

// ---------------- 4) gate + combine: register-blocked 4x4 dual-GEMM ----------------
// SWIZ: float4-granular index into a 64x64 tile stored as 64 rows x 16 float4,
// column swizzled by row so row starts spread across all 8 quad-banks.
#define SWIZ(r, c4) (((r) << 4) + (((c4) ^ ((r) & 7))))

__global__ __launch_bounds__(256, 2)
void combine_kernel(const float* __restrict__ Wa, const float* __restrict__ Wab,
                    const float* __restrict__ Wb, const float* __restrict__ Wbb,
                    float* __restrict__ out, __nv_bfloat16* __restrict__ out_bf) {
    extern __shared__ float sm[];
    float4* sWa = (float4*)sm;            // 1024 float4 (64x64)
    float4* sWb = sWa + 1024;
    float4* sKg = sWb + 1024;
    float4* sAg = sKg + 1024;
    float*  sab = (float*)(sAg + 1024);   // 64
    float*  sbb = sab + 64;               // 64

    int tid = threadIdx.x;
    int item0 = blockIdx.x * 64;

    for (int i = tid; i < 1024; i += 256) {
        int r = i >> 4, c4 = i & 15;
        float4 a = __ldg((const float4*)&Wa[r * DD + c4 * 4]);
        float4 b = __ldg((const float4*)&Wb[r * DD + c4 * 4]);
        sWa[SWIZ(r, c4)] = a;
        sWb[SWIZ(r, c4)] = b;
        int item = item0 + r;
        float4 k = make_float4(0.f, 0.f, 0.f, 0.f);
        float4 g = make_float4(0.f, 0.f, 0.f, 0.f);
        if (item < NI) {
            k = *(const float4*)&g_kg[item * DD + c4 * 4];
            g = *(const float4*)&g_aggi[item * DD + c4 * 4];
        }
        sKg[SWIZ(r, c4)] = k;
        sAg[SWIZ(r, c4)] = g;
    }
    if (tid < DD) { sab[tid] = __ldg(&Wab[tid]); sbb[tid] = __ldg(&Wbb[tid]); }
    __syncthreads();

    // thread owns outputs o = to + 16*oi, items j = tj + 16*ji  (strided blocking)
    int to = tid & 15, tj = tid >> 4;
    float accA[4][4], accB[4][4];
    #pragma unroll
    for (int a = 0; a < 4; a++)
        #pragma unroll
        for (int b = 0; b < 4; b++) { accA[a][b] = 0.f; accB[a][b] = 0.f; }

    #pragma unroll
    for (int d4 = 0; d4 < 16; d4++) {
        float4 wa[4], wb[4], kg[4], ag[4];
        #pragma unroll
        for (int x = 0; x < 4; x++) {
            wa[x] = sWa[SWIZ(to + 16 * x, d4)];
            wb[x] = sWb[SWIZ(to + 16 * x, d4)];
            kg[x] = sKg[SWIZ(tj + 16 * x, d4)];
            ag[x] = sAg[SWIZ(tj + 16 * x, d4)];
        }
        #pragma unroll
        for (int oi = 0; oi < 4; oi++)
            #pragma unroll
            for (int ji = 0; ji < 4; ji++) {
                accA[oi][ji] += wa[oi].x * kg[ji].x + wa[oi].y * kg[ji].y
                              + wa[oi].z * kg[ji].z + wa[oi].w * kg[ji].w;
                accB[oi][ji] += wb[oi].x * ag[ji].x + wb[oi].y * ag[ji].y
                              + wb[oi].z * ag[ji].z + wb[oi].w * ag[ji].w;
            }
    }

    const float* sKgf = (const float*)sKg;
    const float* sAgf = (const float*)sAg;
    #pragma unroll
    for (int ji = 0; ji < 4; ji++) {
        int j = tj + 16 * ji;
        int item = item0 + j;
        if (item < NI) {
            #pragma unroll
            for (int oi = 0; oi < 4; oi++) {
                int o = to + 16 * oi;
                float kv = sKgf[SWIZ(j, o >> 2) * 4 + (o & 3)];
                float av = sAgf[SWIZ(j, o >> 2) * 4 + (o & 3)];
                float z = accA[oi][ji] + sab[o] + accB[oi][ji] + sbb[o];
                float gate = 1.f / (1.f + __expf(-z));
                float res = gate * kv + (1.f - gate) * av;
                out[item * DD + o] = res;
                out_bf[item * DD + o] = __float2bfloat16_rn(res);
            }
        }
    }
}

// ---------------- 5) loss reduction ----------------
__global__ void zero_acc_kernel() { g_acc[0] = 0.0; g_acc[1] = 0.0; }

__global__ void loss_kernel(const float* __restrict__ uemb, const float* __restrict__ iemb,
                            const float* __restrict__ U0, const float* __restrict__ U1,
                            const float* __restrict__ I0, const float* __restrict__ I1,
                            const int* __restrict__ user, const int* __restrict__ pos,
                            const int* __restrict__ neg) {
    int warp = (blockIdx.x * blockDim.x + threadIdx.x) >> 5;
    int lane = threadIdx.x & 31;
    if (warp >= NB) return;
    int u = __ldg(&user[warp]), p = __ldg(&pos[warp]), n = __ldg(&neg[warp]);
    int du = u * DD + lane * 2, dp = p * DD + lane * 2, dn = n * DD + lane * 2;

    float2 a = *(const float2*)&uemb[du];
    float2 b = *(const float2*)&U0[du];
    float2 c = *(const float2*)&U1[du];
    float2 ue = make_float2(a.x + b.x + c.x, a.y + b.y + c.y);

    a = *(const float2*)&iemb[dp]; b = *(const float2*)&I0[dp]; c = *(const float2*)&I1[dp];
    float2 pe = make_float2(a.x + b.x + c.x, a.y + b.y + c.y);

    a = *(const float2*)&iemb[dn]; b = *(const float2*)&I0[dn]; c = *(const float2*)&I1[dn];
    float2 ne = make_float2(a.x + b.x + c.x, a.y + b.y + c.y);

    float ps = ue.x * pe.x + ue.y * pe.y;
    float ns = ue.x * ne.x + ue.y * ne.y;
    float l2 = ue.x * ue.x + ue.y * ue.y + pe.x * pe.x + pe.y * pe.y + ne.x * ne.x + ne.y * ne.y;
    #pragma unroll
    for (int off = 16; off; off >>= 1) {
        ps += __shfl_xor_sync(0xffffffffu, ps, off);
        ns += __shfl_xor_sync(0xffffffffu, ns, off);
        l2 += __shfl_xor_sync(0xffffffffu, l2, off);
    }
    if (lane == 0) {
        float diff = ps - ns;
        float sig = 1.f / (1.f + expf(-diff));
        atomicAdd(&g_acc[0], (double)logf(sig + 1e-10f));
        atomicAdd(&g_acc[1], (double)l2);
    }
}

__global__ void final_kernel(float* __restrict__ out) {
    double bpr = -g_acc[0] / (double)NB;
    double l2  = g_acc[1] / (double)NB;
    out[0] = (float)(bpr + (double)REG * l2);
}

// ---------------- host ----------------
extern "C" void kernel_launch(void* const* d_in, const int* in_sizes, int n_in,
                              void* d_out, int out_size) {
    const float* user_emb = (const float*)d_in[0];
    const float* item_emb = (const float*)d_in[1];
    const float* ent_emb  = (const float*)d_in[2];
    const float* rel_emb  = (const float*)d_in[3];
    const float* Wk  = (const float*)d_in[4];
    const float* Wkb = (const float*)d_in[5];
    const float* Wa  = (const float*)d_in[6];
    const float* Wab = (const float*)d_in[7];
    const float* Wb  = (const float*)d_in[8];
    const float* Wbb = (const float*)d_in[9];
    const float* enorm = (const float*)d_in[10];
    const int* user = (const int*)d_in[11];
    const int* pos  = (const int*)d_in[12];
    const int* neg  = (const int*)d_in[13];
    const int* eu   = (const int*)d_in[14];
    const int* ei   = (const int*)d_in[15];
    const int* kgr  = (const int*)d_in[16];
    const int* kge  = (const int*)d_in[17];

    void* p;
    cudaGetSymbolAddress(&p, g_aggu);
    float* aggu0 = (float*)p;
    float* aggu1 = aggu0 + (size_t)NU * DD;
    cudaGetSymbolAddress(&p, g_inext);
    float* in0 = (float*)p;
    float* in1 = in0 + (size_t)NI * DD;
    cudaGetSymbolAddress(&p, g_aggi);
    float* aggi = (float*)p;
    cudaGetSymbolAddress(&p, g_ub);
    __nv_bfloat16* ub = (__nv_bfloat16*)p;
    cudaGetSymbolAddress(&p, g_ib);
    __nv_bfloat16* ib = (__nv_bfloat16*)p;

    const int ATTN_WPB = 8;
    const int attn_grid = (NI + ATTN_WPB - 1) / ATTN_WPB;
    const int edge_grid = ((NEDGE / 4) * 16) / 256;  // 500K edge-quads * 16 lanes / 256
    const int comb_grid = (NI + 63) / 64;
    const int comb_smem = 4096 * 16 + 128 * 4;       // 64.5 KB dynamic
    const int NU4 = NU * DD / 4, NI4 = NI * DD / 4;

    cudaFuncSetAttribute(combine_kernel, cudaFuncAttributeMaxDynamicSharedMemorySize, comb_smem);

    // launches 1-5 before layer-0 edge (#6, the profiled one)
    zero_acc_kernel<<<1, 1>>>();                                        // 1
    tobf16_kernel<<<(NU4 + 255) / 256, 256>>>(user_emb, ub, NU4);       // 2
    tobf16_kernel<<<(NI4 + 255) / 256, 256>>>(item_emb, ib, NI4);       // 3

    for (int l = 0; l < NL; l++) {
        const float* icur = (l == 0) ? item_emb : in0;
        float* aggu  = (l == 0) ? aggu0 : aggu1;
        float* inext = (l == 0) ? in0 : in1;

        if (l == 1) tobf16_kernel<<<(NU4 + 255) / 256, 256>>>(aggu0, ub, NU4);

        cudaMemsetAsync(aggu, 0, (size_t)NU * DD * sizeof(float));      // 4
        cudaMemsetAsync(aggi, 0, (size_t)NI * DD * sizeof(float));      // 5
        edge_kernel<<<edge_grid, 256>>>(ub, ib, eu, ei, enorm, aggu, aggi);  // 6 (l=0)
        rw_kernel<<<NR, DD>>>(rel_emb, Wk + (size_t)l * DD * 2 * DD, Wkb + (size_t)l * DD);
        attn_kernel<<<attn_grid, 32 * ATTN_WPB>>>(icur, ent_emb, kgr, kge);
        combine_kernel<<<comb_grid, 256, comb_smem>>>(Wa + (size_t)l * DD * DD, Wab + (size_t)l * DD,
                                                      Wb + (size_t)l * DD * DD, Wbb + (size_t)l * DD,
                                                      inext, ib);
    }

    loss_kernel<<<NB / 8, 256>>>(user_emb, item_emb, aggu0, aggu1, in0, in1, user, pos, neg);
    final_kernel<<<1, 1>>>((float*)d_out);
}